// round 11
// baseline (speedup 1.0000x reference)
#include <cuda_runtime.h>
#include <cstdint>

#define N_NODES 100000
#define N_EDGES 600000

typedef unsigned long long ull;

// Scratch: per-node projections, [node][0..9] = h·W1^T, [node][10..19] = h·W2^T
__device__ float g_P[N_NODES * 20];
__device__ int g_shift;   // 0 if src/dst are int32, 1 if int64 (index via e<<shift)

__device__ __forceinline__ void ffma2(ull &acc, ull a, ull b) {
    asm("fma.rn.f32x2 %0, %1, %2, %0;" : "+l"(acc) : "l"(a), "l"(b));
}
__device__ __forceinline__ float pairsum(ull a) {
    unsigned lo, hi;
    asm("mov.b64 {%0,%1}, %2;" : "=r"(lo), "=r"(hi) : "l"(a));
    return __uint_as_float(lo) + __uint_as_float(hi);
}

// ---------------------------------------------------------------------------
// Kernel A: per-(node, half) projection. Work unit u in [0, 2*N_NODES):
//   n = u>>1, half = u&1;  P[n][half*10 + c] = h[n] · W_w[c][half*128 .. +128]
// One warp per unit. lane = cg(1b)*16 + r(4b): cg picks 5 of 10 c's, r picks
// 8 floats (2 float4, k-interleaved as float4 idx q*16+r). Warp-total weight
// regs = 10*128/32 = 40 floats/lane -> ~78 regs total -> 3 blocks/SM.
// Each LDG.128 instruction: 16 lanes read 256B contiguous; both cg groups
// read identical addresses -> coalescer merges.
// Block 0 also detects int32-vs-int64 indices (odd 32-bit words of an int64
// index array are all zero since indices < 2^17).
// ---------------------------------------------------------------------------
__global__ void __launch_bounds__(256, 3) node_proj_kernel(
    const float* __restrict__ h, const float* __restrict__ W,
    const unsigned* __restrict__ srcu)
{
    if (blockIdx.x == 0 && threadIdx.x < 32) {
        unsigned v = srcu[2 * threadIdx.x + 1];
        unsigned any = __ballot_sync(0xffffffffu, v != 0u);
        if (threadIdx.x == 0) g_shift = any ? 0 : 1;
    }

    const int l  = threadIdx.x & 31;
    const int cg = l >> 4;
    const int r  = l & 15;
    const int warp   = (blockIdx.x * blockDim.x + threadIdx.x) >> 5;
    const int nwarps = (gridDim.x * blockDim.x) >> 5;

    for (int u = warp; u < 2 * N_NODES; u += nwarps) {
        const int n    = u >> 1;
        const int half = u & 1;

        // weights: c = cg*5+i, k-slice float4 idx q*16+r  (re-loaded per unit
        // since 'half' varies; hits L1/L2 every time after first touch)
        ull w[5][4];
#pragma unroll
        for (int i = 0; i < 5; i++) {
            const ulonglong2* wp =
                (const ulonglong2*)(W + (cg * 5 + i) * 384 + half * 128);
#pragma unroll
            for (int q = 0; q < 2; q++) {
                ulonglong2 t = wp[q * 16 + r];
                w[i][2 * q]     = t.x;
                w[i][2 * q + 1] = t.y;
            }
        }

        const ulonglong2* hp = (const ulonglong2*)(h + (size_t)n * 128);
        ull x[4];
#pragma unroll
        for (int q = 0; q < 2; q++) {
            ulonglong2 t = hp[q * 16 + r];
            x[2 * q]     = t.x;
            x[2 * q + 1] = t.y;
        }

        ull acc[5] = {0ull, 0ull, 0ull, 0ull, 0ull};
#pragma unroll
        for (int i = 0; i < 5; i++)
#pragma unroll
            for (int q = 0; q < 4; q++)
                ffma2(acc[i], x[q], w[i][q]);

        float sc[5];
#pragma unroll
        for (int i = 0; i < 5; i++) sc[i] = pairsum(acc[i]);
#pragma unroll
        for (int m = 1; m <= 8; m <<= 1)
#pragma unroll
            for (int i = 0; i < 5; i++)
                sc[i] += __shfl_xor_sync(0xffffffffu, sc[i], m);

        if (r < 5) {
            float v = sc[0];
            if (r == 1) v = sc[1];
            else if (r == 2) v = sc[2];
            else if (r == 3) v = sc[3];
            else if (r == 4) v = sc[4];
            g_P[n * 20 + half * 10 + cg * 5 + r] = v;
        }
    }
}

// ---------------------------------------------------------------------------
// Kernel B: out[e][c] = edge_h[e]·W3[c] + P[src[e]][c] + P[dst[e]][10+c] + b[c]
// One warp per edge, same lane layout as kernel A. Weights (W3 slice) are
// loop-invariant -> loaded once in the prologue, amortized by the persistent
// grid-stride loop.
// ---------------------------------------------------------------------------
__global__ void __launch_bounds__(256, 3) edge_score_kernel(
    const float* __restrict__ eh, const float* __restrict__ W,
    const float* __restrict__ bvec, const int* __restrict__ src,
    const int* __restrict__ dst, float* __restrict__ out)
{
    const int l  = threadIdx.x & 31;
    const int cg = l >> 4;
    const int r  = l & 15;
    const int warp   = (blockIdx.x * blockDim.x + threadIdx.x) >> 5;
    const int nwarps = (gridDim.x * blockDim.x) >> 5;
    const int shift  = g_shift;

    ull w[5][4];
#pragma unroll
    for (int i = 0; i < 5; i++) {
        const ulonglong2* wp = (const ulonglong2*)(W + (cg * 5 + i) * 384 + 256);
#pragma unroll
        for (int q = 0; q < 2; q++) {
            ulonglong2 t = wp[q * 16 + r];
            w[i][2 * q]     = t.x;
            w[i][2 * q + 1] = t.y;
        }
    }
    const int   myc  = cg * 5 + r;                        // valid when r < 5
    const float bias = (r < 5) ? __ldg(bvec + myc) : 0.0f;

    for (int e = warp; e < N_EDGES; e += nwarps) {
        // L2-resident random gathers issued first to overlap with streaming
        float pv = 0.0f;
        if (r < 5) {
            int s = __ldg(src + ((size_t)e << shift));
            int d = __ldg(dst + ((size_t)e << shift));
            pv = g_P[s * 20 + myc] + g_P[d * 20 + 10 + myc] + bias;
        }

        const ulonglong2* xp = (const ulonglong2*)(eh + (size_t)e * 128);
        ull x[4];
#pragma unroll
        for (int q = 0; q < 2; q++) {
            ulonglong2 t = xp[q * 16 + r];
            x[2 * q]     = t.x;
            x[2 * q + 1] = t.y;
        }

        ull acc[5] = {0ull, 0ull, 0ull, 0ull, 0ull};
#pragma unroll
        for (int i = 0; i < 5; i++)
#pragma unroll
            for (int q = 0; q < 4; q++)
                ffma2(acc[i], x[q], w[i][q]);

        float sc[5];
#pragma unroll
        for (int i = 0; i < 5; i++) sc[i] = pairsum(acc[i]);
#pragma unroll
        for (int m = 1; m <= 8; m <<= 1)
#pragma unroll
            for (int i = 0; i < 5; i++)
                sc[i] += __shfl_xor_sync(0xffffffffu, sc[i], m);

        if (r < 5) {
            float v = sc[0];
            if (r == 1) v = sc[1];
            else if (r == 2) v = sc[2];
            else if (r == 3) v = sc[3];
            else if (r == 4) v = sc[4];
            out[(size_t)e * 10 + myc] = v + pv;
        }
    }
}

extern "C" void kernel_launch(void* const* d_in, const int* in_sizes, int n_in,
                              void* d_out, int out_size)
{
    const float* h    = (const float*)d_in[0];   // [100000, 128]
    const float* eh   = (const float*)d_in[1];   // [600000, 1, 128]
    const float* W_w  = (const float*)d_in[2];   // [10, 384]
    const float* W_b  = (const float*)d_in[3];   // [10]
    const int*   src  = (const int*)d_in[4];     // [600000] int32 or int64
    const int*   dst  = (const int*)d_in[5];     // [600000]
    float*       out  = (float*)d_out;           // [600000, 10]

    // 148 SMs x 3 blocks = 444 blocks: one persistent wave per kernel
    node_proj_kernel<<<444, 256>>>(h, W_w, (const unsigned*)d_in[4]);
    edge_score_kernel<<<444, 256>>>(eh, W_w, W_b, src, dst, out);
}